// round 11
// baseline (speedup 1.0000x reference)
#include <cuda_runtime.h>
#include <cuda_fp16.h>
#include <math.h>

// TropicalHashGrid: 16-level hash-grid encoding, N=2^21 points, F=2 feats/level.
// Levels 0-5 via dense cube tables (level 5 baked from its hash),
// levels 6-15 spatially hashed. fp16 tables (tcnn-style).
//
// R11 changes vs R10 (469us; pinned at l1tex wavefront floor, hash E=4.65):
//  - mirror-pair tables P3 (m=7: pairs (8g+t, 8g+7-t)) and P4 (m=15) make
//    every m<=15 x-corner pair ONE 16B load. Only m>=31 (1/16) stays scalar.
//    E[wf]/hash level 4.65 -> 4.25.
//  - copy-B dropped (fully subsumed by P3/P4)
//  - single fused hash prologue builds A+P3+P4 from one 16-entry read

#define L_LEVELS   16
#define HASHMAP_SZ (1u << 19)
#define HASH_MASK  (HASHMAP_SZ - 1u)
#define P_PER      (1 << 17)                // uint4 entries per level in P3/P4
#define PRIME_Y    2654435761u
#define PRIME_Z    805459861u
#define NUM_DENSE  6                        // levels 0..5 via cube tables
#define NUM_HASH   (L_LEVELS - NUM_DENSE)   // 10
#define BLOCK_T    128

// Scratch (static __device__: allocation-free).
#define DENSE_TOTAL_MAX 871000
__device__ __align__(128) uint4 g_dcube[2 * DENSE_TOTAL_MAX];     // ~27.9MB
__device__ __align__(16) unsigned g_hash[NUM_HASH * HASHMAP_SZ];  // 20MB (A)
__device__ __align__(16) uint4    g_p3[NUM_HASH * P_PER];         // 20MB
__device__ __align__(16) uint4    g_p4[NUM_HASH * P_PER];         // 20MB

struct LevelParams {
    float scale[L_LEVELS];
    int   res[L_LEVELS];
    int   doff[NUM_DENSE];
};

// ------------- bit-cast helpers -------------
__device__ __forceinline__ unsigned h2_to_u(__half2 h) {
    return *reinterpret_cast<unsigned*>(&h);
}
__device__ __forceinline__ float2 h2f(unsigned u) {
    return __half22float2(*reinterpret_cast<__half2*>(&u));
}
// Select component j (0..3) of a uint4.
__device__ __forceinline__ unsigned comp4(const uint4 q, unsigned j) {
    const unsigned lo = (j & 1u) ? q.y : q.x;
    const unsigned hi = (j & 1u) ? q.w : q.z;
    return (j & 2u) ? hi : lo;
}

// ------------- prologue 1: fp16 hash table A + mirror-pair tables P3/P4 ------
// One thread per (level, 16-entry group). P3 packs pairs (T[8g+t], T[8g+7-t]),
// P4 packs (T[16G+t], T[16G+15-t]), two pairs per uint4 (t even in comps 0/1,
// t odd in comps 2/3).
__global__ void build_hash_kernel(const float* __restrict__ table)
{
    const int i = blockIdx.x * blockDim.x + threadIdx.x;
    if (i >= NUM_HASH * (1 << 15)) return;
    const int lvl = i >> 15;
    const int G   = i & ((1 << 15) - 1);
    const float2* __restrict__ src =
        reinterpret_cast<const float2*>(table)
        + (size_t)(lvl + NUM_DENSE) * HASHMAP_SZ + ((size_t)G << 4);

    unsigned e[16];
    #pragma unroll
    for (int k = 0; k < 16; ++k) {
        const float2 v = src[k];
        e[k] = h2_to_u(__floats2half2_rn(v.x, v.y));
    }

    uint4* __restrict__ A4 =
        reinterpret_cast<uint4*>(g_hash + (size_t)lvl * HASHMAP_SZ);
    #pragma unroll
    for (int q = 0; q < 4; ++q)
        A4[(G << 2) + q] = make_uint4(e[4*q], e[4*q+1], e[4*q+2], e[4*q+3]);

    uint4* __restrict__ P3 = g_p3 + (size_t)lvl * P_PER;
    #pragma unroll
    for (int g2 = 0; g2 < 2; ++g2) {           // two 8-groups per 16-group
        const int b = 8 * g2;
        #pragma unroll
        for (int h = 0; h < 2; ++h)
            P3[((2*G + g2) << 1) + h] = make_uint4(
                e[b + 2*h], e[b + 7 - 2*h], e[b + 2*h + 1], e[b + 6 - 2*h]);
    }

    uint4* __restrict__ P4 = g_p4 + (size_t)lvl * P_PER;
    #pragma unroll
    for (int h = 0; h < 4; ++h)
        P4[(G << 2) + h] = make_uint4(
            e[2*h], e[15 - 2*h], e[2*h + 1], e[14 - 2*h]);
}

// ------------- prologue 2: cube tables for clamped dense levels 0-4 ---------
__global__ void build_dense_kernel(const float* __restrict__ table,
                                   LevelParams lp, int total)
{
    const int i = blockIdx.x * blockDim.x + threadIdx.x;
    if (i >= total) return;
    int l = 0;
    #pragma unroll
    for (int k = 1; k < 5; ++k) if (i >= lp.doff[k]) l = k;
    const int flat = i - lp.doff[l];
    const int res  = lp.res[l];
    const int r2   = res * res;
    const int z    = flat / r2;
    const int rem  = flat - z * r2;
    const int y    = rem / res;
    const int x    = rem - y * res;
    const int x1   = min(x + 1, res - 1);
    const int y1   = min(y + 1, res - 1);
    const int z1   = min(z + 1, res - 1);
    const float2* __restrict__ tbl =
        reinterpret_cast<const float2*>(table) + (size_t)l * HASHMAP_SZ;
    #pragma unroll
    for (int h = 0; h < 2; ++h) {
        const int zz = (h ? z1 : z) * r2;
        const float2 c00 = tbl[x  + y  * res + zz];
        const float2 c10 = tbl[x1 + y  * res + zz];
        const float2 c01 = tbl[x  + y1 * res + zz];
        const float2 c11 = tbl[x1 + y1 * res + zz];
        uint4 q;
        q.x = h2_to_u(__floats2half2_rn(c00.x, c00.y));
        q.y = h2_to_u(__floats2half2_rn(c10.x, c10.y));
        q.z = h2_to_u(__floats2half2_rn(c01.x, c01.y));
        q.w = h2_to_u(__floats2half2_rn(c11.x, c11.y));
        g_dcube[2 * i + h] = q;
    }
}

// ------------- prologue 3: cube table for level 5 (hashed corners) ----------
__global__ void build_dense5_kernel(const float* __restrict__ table,
                                    int res, int doff5, int total)
{
    const int i = blockIdx.x * blockDim.x + threadIdx.x;
    if (i >= total) return;
    const int r2  = res * res;
    const int z   = i / r2;
    const int rem = i - z * r2;
    const int y   = rem / res;
    const int x   = rem - y * res;
    const float2* __restrict__ tbl =
        reinterpret_cast<const float2*>(table) + (size_t)5 * HASHMAP_SZ;
    const unsigned hx0 = (unsigned)x,            hx1 = hx0 + 1u;
    const unsigned hy0 = (unsigned)y * PRIME_Y,  hy1 = hy0 + PRIME_Y;
    #pragma unroll
    for (int h = 0; h < 2; ++h) {
        const unsigned hz = ((unsigned)z + (unsigned)h) * PRIME_Z;
        const float2 c00 = tbl[(hx0 ^ hy0 ^ hz) & HASH_MASK];
        const float2 c10 = tbl[(hx1 ^ hy0 ^ hz) & HASH_MASK];
        const float2 c01 = tbl[(hx0 ^ hy1 ^ hz) & HASH_MASK];
        const float2 c11 = tbl[(hx1 ^ hy1 ^ hz) & HASH_MASK];
        uint4 q;
        q.x = h2_to_u(__floats2half2_rn(c00.x, c00.y));
        q.y = h2_to_u(__floats2half2_rn(c10.x, c10.y));
        q.z = h2_to_u(__floats2half2_rn(c01.x, c01.y));
        q.w = h2_to_u(__floats2half2_rn(c11.x, c11.y));
        g_dcube[2 * (doff5 + i) + h] = q;
    }
}

// ------------- main kernel -------------
__global__ void __launch_bounds__(BLOCK_T, 8)
hashgrid_kernel(const float* __restrict__ xs,
                float* __restrict__ out,
                int n, LevelParams lp)
{
    __shared__ float sbuf[BLOCK_T * 33];   // coords, then results (stride 33)

    const int tid  = threadIdx.x;
    const int lane = tid & 31;
    const int wrow = (tid >> 5) * 32;      // warp's first row within block
    const int p0   = blockIdx.x * BLOCK_T;
    const int pt   = p0 + tid;

    float px, py, pz;
    if (p0 + BLOCK_T <= n) {
        if (tid < 96) {
            const float4 v = __ldg(reinterpret_cast<const float4*>(
                                       xs + (size_t)p0 * 3) + tid);
            reinterpret_cast<float4*>(sbuf)[tid] = v;
        }
        __syncthreads();
        px = sbuf[tid * 3 + 0];
        py = sbuf[tid * 3 + 1];
        pz = sbuf[tid * 3 + 2];
        __syncthreads();
    } else {
        const int ptc = (pt < n) ? pt : (n - 1);
        px = xs[(size_t)ptc * 3 + 0];
        py = xs[(size_t)ptc * 3 + 1];
        pz = xs[(size_t)ptc * 3 + 2];
    }

    // ---- Dense-treated levels 0..5: 32B cube entry, lane-pair loads ----
    #pragma unroll 1
    for (int l = 0; l < NUM_DENSE; ++l) {
        const float scale = lp.scale[l];
        const int   res   = lp.res[l];

        // Unfused mul+add to match reference elementwise x*scale + 0.5.
        const float posx = __fadd_rn(__fmul_rn(px, scale), 0.5f);
        const float posy = __fadd_rn(__fmul_rn(py, scale), 0.5f);
        const float posz = __fadd_rn(__fmul_rn(pz, scale), 0.5f);
        const float pfx = floorf(posx), pfy = floorf(posy), pfz = floorf(posz);
        const float fx = posx - pfx, fy = posy - pfy, fz = posz - pfz;
        const int gx = (int)pfx, gy = (int)pfy, gz = (int)pfz;
        const int base = lp.doff[l] + gx + (gy + gz * res) * res;

        #pragma unroll
        for (int p = 0; p < 2; ++p) {
            const int   q   = 16 * p + (lane >> 1);
            const int   bq  = __shfl_sync(0xffffffffu, base, q);
            const float qfx = __shfl_sync(0xffffffffu, fx, q);
            const float qfy = __shfl_sync(0xffffffffu, fy, q);
            const float qfz = __shfl_sync(0xffffffffu, fz, q);

            const uint4 h = __ldg(g_dcube + 2 * bq + (lane & 1));

            const float wz  = (lane & 1) ? qfz : (1.0f - qfz);
            const float wx1 = qfx, wx0 = 1.0f - qfx;
            const float wy1 = qfy, wy0 = 1.0f - qfy;
            const float w00 = wx0 * wy0 * wz, w10 = wx1 * wy0 * wz;
            const float w01 = wx0 * wy1 * wz, w11 = wx1 * wy1 * wz;
            const float2 c00 = h2f(h.x), c10 = h2f(h.y);
            const float2 c01 = h2f(h.z), c11 = h2f(h.w);

            float rx = w00 * c00.x;
            float ry = w00 * c00.y;
            rx = fmaf(w10, c10.x, rx); ry = fmaf(w10, c10.y, ry);
            rx = fmaf(w01, c01.x, rx); ry = fmaf(w01, c01.y, ry);
            rx = fmaf(w11, c11.x, rx); ry = fmaf(w11, c11.y, ry);

            rx += __shfl_xor_sync(0xffffffffu, rx, 1);
            ry += __shfl_xor_sync(0xffffffffu, ry, 1);

            if ((lane & 1) == 0) {
                const int row = wrow + q;
                sbuf[row * 33 + 2 * l + 0] = rx;
                sbuf[row * 33 + 2 * l + 1] = ry;
            }
        }
    }

    // ---- Hash levels 6..15: idx = (x ^ y*P1 ^ z*P2) & mask ----
    // x-corner pair (a, a^m), m = hx^(hx+1) = 2^k-1:
    //   m<=3  -> aligned 4-group of A        (one LDG.128)
    //   m==7  -> mirror pair in P3           (one LDG.128)
    //   m==15 -> mirror pair in P4           (one LDG.128)
    //   m>=31 -> two scalar loads (prob 1/16)
    #pragma unroll 1
    for (int l = NUM_DENSE; l < L_LEVELS; ++l) {
        const int hl = l - NUM_DENSE;
        const unsigned* __restrict__ tbl = g_hash + (size_t)hl * HASHMAP_SZ;
        const uint4* __restrict__ tA = reinterpret_cast<const uint4*>(tbl);
        const uint4* __restrict__ t3 = g_p3 + (size_t)hl * P_PER;
        const uint4* __restrict__ t4 = g_p4 + (size_t)hl * P_PER;
        const float scale = lp.scale[l];

        const float posx = __fadd_rn(__fmul_rn(px, scale), 0.5f);
        const float posy = __fadd_rn(__fmul_rn(py, scale), 0.5f);
        const float posz = __fadd_rn(__fmul_rn(pz, scale), 0.5f);
        const float pfx = floorf(posx), pfy = floorf(posy), pfz = floorf(posz);
        const float fx = posx - pfx, fy = posy - pfy, fz = posz - pfz;

        const unsigned hx0 = (unsigned)(int)pfx;
        const unsigned hx1 = hx0 + 1u;
        const unsigned hy0 = (unsigned)(int)pfy * PRIME_Y;
        const unsigned hy1 = hy0 + PRIME_Y;
        const unsigned hz0 = (unsigned)(int)pfz * PRIME_Z;
        const unsigned hz1 = hz0 + PRIME_Z;

        const unsigned m  = hx0 ^ hx1;         // 1,3,7,15,31,...
        const bool mA  = (m <= 3u);
        const bool m7  = (m == 7u);
        const bool prd = (m <= 15u);           // paired via A/P3/P4

        unsigned av[4], s0[4], s1[4];
        const uint4* gp[4];
        {
            const unsigned hyz[4] = { hy0 ^ hz0, hy0 ^ hz1,
                                      hy1 ^ hz0, hy1 ^ hz1 };
            #pragma unroll
            for (int c = 0; c < 4; ++c) {
                const unsigned a = (hx0 ^ hyz[c]) & HASH_MASK;
                av[c] = a;
                const unsigned j7  = a & 7u;
                const unsigned j15 = a & 15u;
                const unsigned t7  = min(j7,  7u  - j7);
                const unsigned t15 = min(j15, 15u - j15);
                const unsigned offA = a >> 2;
                const unsigned off3 = ((a >> 3) << 1) | (t7 >> 1);
                const unsigned off4 = ((a >> 4) << 2) | (t15 >> 1);
                const unsigned sA = a & 3u;
                const unsigned s3 = ((t7  & 1u) << 1) | (unsigned)(j7  >= 4u);
                const unsigned s4 = ((t15 & 1u) << 1) | (unsigned)(j15 >= 8u);
                const unsigned off = mA ? offA : (m7 ? off3 : off4);
                const unsigned s   = mA ? sA   : (m7 ? s3   : s4);
                gp[c] = (mA ? tA : (m7 ? t3 : t4)) + off;
                s0[c] = s;
                s1[c] = mA ? (s ^ m) : (s ^ 1u);
            }
        }

        // Issue all loads back-to-back (predicated) to keep MLP high.
        uint4 qv[4];
        #pragma unroll
        for (int c = 0; c < 4; ++c) if (prd) qv[c] = __ldg(gp[c]);
        unsigned u0[4], u1[4];
        #pragma unroll
        for (int c = 0; c < 4; ++c) {
            if (!prd) {
                u0[c] = __ldg(tbl + av[c]);
                u1[c] = __ldg(tbl + ((av[c] ^ m) & HASH_MASK));
            }
        }

        float2 f[8];
        #pragma unroll
        for (int c = 0; c < 4; ++c) {
            if (prd) {
                f[c]     = h2f(comp4(qv[c], s0[c]));
                f[4 + c] = h2f(comp4(qv[c], s1[c]));
            } else {
                f[c]     = h2f(u0[c]);
                f[4 + c] = h2f(u1[c]);
            }
        }

        // Trilinear blend (z fastest among the 4 combos, x split at f[4..7]).
        const float wx1 = fx, wx0 = 1.0f - fx;
        const float wy1 = fy, wy0 = 1.0f - fy;
        const float wz1 = fz, wz0 = 1.0f - fz;
        const float wxy00 = wx0 * wy0, wxy01 = wx0 * wy1;
        const float wxy10 = wx1 * wy0, wxy11 = wx1 * wy1;
        float w[8];
        w[0] = wxy00 * wz0; w[1] = wxy00 * wz1;
        w[2] = wxy01 * wz0; w[3] = wxy01 * wz1;
        w[4] = wxy10 * wz0; w[5] = wxy10 * wz1;
        w[6] = wxy11 * wz0; w[7] = wxy11 * wz1;

        float r0 = w[0] * f[0].x;
        float r1 = w[0] * f[0].y;
        #pragma unroll
        for (int j = 1; j < 8; ++j) {
            r0 = fmaf(w[j], f[j].x, r0);
            r1 = fmaf(w[j], f[j].y, r1);
        }

        sbuf[tid * 33 + 2 * l + 0] = r0;
        sbuf[tid * 33 + 2 * l + 1] = r1;
    }

    __syncthreads();

    // Coalesced copy-out; streaming stores keep tables resident in L2.
    const int nvalid = min(BLOCK_T, n - p0);
    float* __restrict__ ob = out + (size_t)p0 * 32;
    const int total = nvalid * 32;
    #pragma unroll 4
    for (int k = tid; k < total; k += BLOCK_T) {
        __stcs(ob + k, sbuf[(k >> 5) * 33 + (k & 31)]);
    }
}

extern "C" void kernel_launch(void* const* d_in, const int* in_sizes, int n_in,
                              void* d_out, int out_size)
{
    const int n = out_size / (L_LEVELS * 2);   // out is [N, 32] float32

    const float* x   = (const float*)d_in[0];
    const float* tbl = (const float*)d_in[1];
    if (n_in >= 2 && in_sizes[0] != n * 3) {
        x   = (const float*)d_in[1];
        tbl = (const float*)d_in[0];
    }

    LevelParams lp;
    const double B = pow(2.0, 7.0 / 15.0);     // log2(2048/16)/15
    int off = 0;
    for (int l = 0; l < L_LEVELS; ++l) {
        const double s = 16.0 * pow(B, (double)l) - 1.0;
        lp.scale[l] = (float)s;
        lp.res[l]   = (int)ceil(s) + 1;
        if (l < NUM_DENSE) {
            lp.doff[l] = off;
            off += lp.res[l] * lp.res[l] * lp.res[l];
        }
    }
    const int total04 = lp.doff[5];            // 330,940 (levels 0-4)
    const int total5  = off - lp.doff[5];      // 531,441 (level 5, res=81)

    // Prologues (same stream; deterministic functions of inputs).
    const int htot = NUM_HASH * (1 << 15);
    build_hash_kernel<<<(htot + 255) / 256, 256>>>(tbl);
    build_dense_kernel<<<(total04 + 255) / 256, 256>>>(tbl, lp, total04);
    build_dense5_kernel<<<(total5 + 255) / 256, 256>>>(
        tbl, lp.res[5], lp.doff[5], total5);

    const int grid = (n + BLOCK_T - 1) / BLOCK_T;
    hashgrid_kernel<<<grid, BLOCK_T>>>(x, (float*)d_out, n, lp);
}

// round 12
// speedup vs baseline: 1.2382x; 1.2382x over previous
#include <cuda_runtime.h>
#include <cuda_fp16.h>
#include <math.h>

// TropicalHashGrid: 16-level hash-grid encoding, N=2^21 points, F=2 feats/level.
// Levels 0-5 via dense cube tables (level 5 baked from its hash),
// levels 6-15 spatially hashed. fp16 tables (tcnn-style).
//
// R12 changes vs R11 (573us REGRESSION from +40MB footprint):
//  - revert to R9/R10 footprint (68MB); replace copy-B with ONE mirror table
//    M16 whose 4-groups {16G: q, 7-q, 8+q, 15-q} contain ALL m=7 AND ALL m=15
//    x-corner pairs -> E[wf]/hash level 4.25 (R11's coverage, R9's footprint).

#define L_LEVELS   16
#define HASHMAP_SZ (1u << 19)
#define HASH_MASK  (HASHMAP_SZ - 1u)
#define P_PER      (1 << 17)                // uint4 entries per level in M16
#define PRIME_Y    2654435761u
#define PRIME_Z    805459861u
#define NUM_DENSE  6                        // levels 0..5 via cube tables
#define NUM_HASH   (L_LEVELS - NUM_DENSE)   // 10
#define BLOCK_T    128

// Scratch (static __device__: allocation-free). Total ~68MB.
#define DENSE_TOTAL_MAX 871000
__device__ __align__(128) uint4 g_dcube[2 * DENSE_TOTAL_MAX];     // ~27.9MB
__device__ __align__(16) unsigned g_hash[NUM_HASH * HASHMAP_SZ];  // 20MB (A)
__device__ __align__(16) uint4    g_m16[NUM_HASH * P_PER];        // 20MB (M16)

struct LevelParams {
    float scale[L_LEVELS];
    int   res[L_LEVELS];
    int   doff[NUM_DENSE];
};

// ------------- bit-cast helpers -------------
__device__ __forceinline__ unsigned h2_to_u(__half2 h) {
    return *reinterpret_cast<unsigned*>(&h);
}
__device__ __forceinline__ float2 h2f(unsigned u) {
    return __half22float2(*reinterpret_cast<__half2*>(&u));
}
// Select component j (0..3) of a uint4.
__device__ __forceinline__ unsigned comp4(const uint4 q, unsigned j) {
    const unsigned lo = (j & 1u) ? q.y : q.x;
    const unsigned hi = (j & 1u) ? q.w : q.z;
    return (j & 2u) ? hi : lo;
}

// ------------- prologue 1: fp16 hash table A + mirror table M16 -------------
// One thread per (level, 16-entry group G).
// M16 group q (q=0..3) = { T[16G+q], T[16G+7-q], T[16G+8+q], T[16G+15-q] }.
__global__ void build_hash_kernel(const float* __restrict__ table)
{
    const int i = blockIdx.x * blockDim.x + threadIdx.x;
    if (i >= NUM_HASH * (1 << 15)) return;
    const int lvl = i >> 15;
    const int G   = i & ((1 << 15) - 1);
    const float2* __restrict__ src =
        reinterpret_cast<const float2*>(table)
        + (size_t)(lvl + NUM_DENSE) * HASHMAP_SZ + ((size_t)G << 4);

    unsigned e[16];
    #pragma unroll
    for (int k = 0; k < 16; ++k) {
        const float2 v = src[k];
        e[k] = h2_to_u(__floats2half2_rn(v.x, v.y));
    }

    uint4* __restrict__ A4 =
        reinterpret_cast<uint4*>(g_hash + (size_t)lvl * HASHMAP_SZ);
    #pragma unroll
    for (int q = 0; q < 4; ++q)
        A4[(G << 2) + q] = make_uint4(e[4*q], e[4*q+1], e[4*q+2], e[4*q+3]);

    uint4* __restrict__ M = g_m16 + (size_t)lvl * P_PER;
    #pragma unroll
    for (int q = 0; q < 4; ++q)
        M[(G << 2) + q] = make_uint4(e[q], e[7 - q], e[8 + q], e[15 - q]);
}

// ------------- prologue 2: cube tables for clamped dense levels 0-4 ---------
__global__ void build_dense_kernel(const float* __restrict__ table,
                                   LevelParams lp, int total)
{
    const int i = blockIdx.x * blockDim.x + threadIdx.x;
    if (i >= total) return;
    int l = 0;
    #pragma unroll
    for (int k = 1; k < 5; ++k) if (i >= lp.doff[k]) l = k;
    const int flat = i - lp.doff[l];
    const int res  = lp.res[l];
    const int r2   = res * res;
    const int z    = flat / r2;
    const int rem  = flat - z * r2;
    const int y    = rem / res;
    const int x    = rem - y * res;
    const int x1   = min(x + 1, res - 1);
    const int y1   = min(y + 1, res - 1);
    const int z1   = min(z + 1, res - 1);
    const float2* __restrict__ tbl =
        reinterpret_cast<const float2*>(table) + (size_t)l * HASHMAP_SZ;
    #pragma unroll
    for (int h = 0; h < 2; ++h) {
        const int zz = (h ? z1 : z) * r2;
        const float2 c00 = tbl[x  + y  * res + zz];
        const float2 c10 = tbl[x1 + y  * res + zz];
        const float2 c01 = tbl[x  + y1 * res + zz];
        const float2 c11 = tbl[x1 + y1 * res + zz];
        uint4 q;
        q.x = h2_to_u(__floats2half2_rn(c00.x, c00.y));
        q.y = h2_to_u(__floats2half2_rn(c10.x, c10.y));
        q.z = h2_to_u(__floats2half2_rn(c01.x, c01.y));
        q.w = h2_to_u(__floats2half2_rn(c11.x, c11.y));
        g_dcube[2 * i + h] = q;
    }
}

// ------------- prologue 3: cube table for level 5 (hashed corners) ----------
__global__ void build_dense5_kernel(const float* __restrict__ table,
                                    int res, int doff5, int total)
{
    const int i = blockIdx.x * blockDim.x + threadIdx.x;
    if (i >= total) return;
    const int r2  = res * res;
    const int z   = i / r2;
    const int rem = i - z * r2;
    const int y   = rem / res;
    const int x   = rem - y * res;
    const float2* __restrict__ tbl =
        reinterpret_cast<const float2*>(table) + (size_t)5 * HASHMAP_SZ;
    const unsigned hx0 = (unsigned)x,            hx1 = hx0 + 1u;
    const unsigned hy0 = (unsigned)y * PRIME_Y,  hy1 = hy0 + PRIME_Y;
    #pragma unroll
    for (int h = 0; h < 2; ++h) {
        const unsigned hz = ((unsigned)z + (unsigned)h) * PRIME_Z;
        const float2 c00 = tbl[(hx0 ^ hy0 ^ hz) & HASH_MASK];
        const float2 c10 = tbl[(hx1 ^ hy0 ^ hz) & HASH_MASK];
        const float2 c01 = tbl[(hx0 ^ hy1 ^ hz) & HASH_MASK];
        const float2 c11 = tbl[(hx1 ^ hy1 ^ hz) & HASH_MASK];
        uint4 q;
        q.x = h2_to_u(__floats2half2_rn(c00.x, c00.y));
        q.y = h2_to_u(__floats2half2_rn(c10.x, c10.y));
        q.z = h2_to_u(__floats2half2_rn(c01.x, c01.y));
        q.w = h2_to_u(__floats2half2_rn(c11.x, c11.y));
        g_dcube[2 * (doff5 + i) + h] = q;
    }
}

// ------------- main kernel -------------
__global__ void __launch_bounds__(BLOCK_T, 8)
hashgrid_kernel(const float* __restrict__ xs,
                float* __restrict__ out,
                int n, LevelParams lp)
{
    __shared__ float sbuf[BLOCK_T * 33];   // coords, then results (stride 33)

    const int tid  = threadIdx.x;
    const int lane = tid & 31;
    const int wrow = (tid >> 5) * 32;      // warp's first row within block
    const int p0   = blockIdx.x * BLOCK_T;
    const int pt   = p0 + tid;

    float px, py, pz;
    if (p0 + BLOCK_T <= n) {
        if (tid < 96) {
            const float4 v = __ldg(reinterpret_cast<const float4*>(
                                       xs + (size_t)p0 * 3) + tid);
            reinterpret_cast<float4*>(sbuf)[tid] = v;
        }
        __syncthreads();
        px = sbuf[tid * 3 + 0];
        py = sbuf[tid * 3 + 1];
        pz = sbuf[tid * 3 + 2];
        __syncthreads();
    } else {
        const int ptc = (pt < n) ? pt : (n - 1);
        px = xs[(size_t)ptc * 3 + 0];
        py = xs[(size_t)ptc * 3 + 1];
        pz = xs[(size_t)ptc * 3 + 2];
    }

    // ---- Dense-treated levels 0..5: 32B cube entry, lane-pair loads ----
    #pragma unroll 1
    for (int l = 0; l < NUM_DENSE; ++l) {
        const float scale = lp.scale[l];
        const int   res   = lp.res[l];

        // Unfused mul+add to match reference elementwise x*scale + 0.5.
        const float posx = __fadd_rn(__fmul_rn(px, scale), 0.5f);
        const float posy = __fadd_rn(__fmul_rn(py, scale), 0.5f);
        const float posz = __fadd_rn(__fmul_rn(pz, scale), 0.5f);
        const float pfx = floorf(posx), pfy = floorf(posy), pfz = floorf(posz);
        const float fx = posx - pfx, fy = posy - pfy, fz = posz - pfz;
        const int gx = (int)pfx, gy = (int)pfy, gz = (int)pfz;
        const int base = lp.doff[l] + gx + (gy + gz * res) * res;

        #pragma unroll
        for (int p = 0; p < 2; ++p) {
            const int   q   = 16 * p + (lane >> 1);
            const int   bq  = __shfl_sync(0xffffffffu, base, q);
            const float qfx = __shfl_sync(0xffffffffu, fx, q);
            const float qfy = __shfl_sync(0xffffffffu, fy, q);
            const float qfz = __shfl_sync(0xffffffffu, fz, q);

            const uint4 h = __ldg(g_dcube + 2 * bq + (lane & 1));

            const float wz  = (lane & 1) ? qfz : (1.0f - qfz);
            const float wx1 = qfx, wx0 = 1.0f - qfx;
            const float wy1 = qfy, wy0 = 1.0f - qfy;
            const float w00 = wx0 * wy0 * wz, w10 = wx1 * wy0 * wz;
            const float w01 = wx0 * wy1 * wz, w11 = wx1 * wy1 * wz;
            const float2 c00 = h2f(h.x), c10 = h2f(h.y);
            const float2 c01 = h2f(h.z), c11 = h2f(h.w);

            float rx = w00 * c00.x;
            float ry = w00 * c00.y;
            rx = fmaf(w10, c10.x, rx); ry = fmaf(w10, c10.y, ry);
            rx = fmaf(w01, c01.x, rx); ry = fmaf(w01, c01.y, ry);
            rx = fmaf(w11, c11.x, rx); ry = fmaf(w11, c11.y, ry);

            rx += __shfl_xor_sync(0xffffffffu, rx, 1);
            ry += __shfl_xor_sync(0xffffffffu, ry, 1);

            if ((lane & 1) == 0) {
                const int row = wrow + q;
                sbuf[row * 33 + 2 * l + 0] = rx;
                sbuf[row * 33 + 2 * l + 1] = ry;
            }
        }
    }

    // ---- Hash levels 6..15: idx = (x ^ y*P1 ^ z*P2) & mask ----
    // x-corner pair (a, a^m), m = hx^(hx+1) = 2^k-1:
    //   m<=3       -> aligned 4-group of A   (one LDG.128); partner slot s^m
    //   m==7,m==15 -> mirror group of M16    (one LDG.128); partner s^1 / s^3
    //   m>=31      -> two scalar loads (prob 1/16)
    #pragma unroll 1
    for (int l = NUM_DENSE; l < L_LEVELS; ++l) {
        const int hl = l - NUM_DENSE;
        const unsigned* __restrict__ tbl = g_hash + (size_t)hl * HASHMAP_SZ;
        const uint4* __restrict__ tA = reinterpret_cast<const uint4*>(tbl);
        const uint4* __restrict__ tM = g_m16 + (size_t)hl * P_PER;
        const float scale = lp.scale[l];

        const float posx = __fadd_rn(__fmul_rn(px, scale), 0.5f);
        const float posy = __fadd_rn(__fmul_rn(py, scale), 0.5f);
        const float posz = __fadd_rn(__fmul_rn(pz, scale), 0.5f);
        const float pfx = floorf(posx), pfy = floorf(posy), pfz = floorf(posz);
        const float fx = posx - pfx, fy = posy - pfy, fz = posz - pfz;

        const unsigned hx0 = (unsigned)(int)pfx;
        const unsigned hx1 = hx0 + 1u;
        const unsigned hy0 = (unsigned)(int)pfy * PRIME_Y;
        const unsigned hy1 = hy0 + PRIME_Y;
        const unsigned hz0 = (unsigned)(int)pfz * PRIME_Z;
        const unsigned hz1 = hz0 + PRIME_Z;

        const unsigned m  = hx0 ^ hx1;         // 1,3,7,15,31,...
        const bool mA  = (m <= 3u);
        const bool prd = (m <= 15u);           // paired via A or M16
        const unsigned sxor = mA ? m : ((m == 7u) ? 1u : 3u);

        unsigned av[4], s0[4];
        const uint4* gp[4];
        {
            const unsigned hyz[4] = { hy0 ^ hz0, hy0 ^ hz1,
                                      hy1 ^ hz0, hy1 ^ hz1 };
            #pragma unroll
            for (int c = 0; c < 4; ++c) {
                const unsigned a = (hx0 ^ hyz[c]) & HASH_MASK;
                av[c] = a;
                const unsigned j7 = a & 7u;
                const unsigned q  = min(j7, 7u - j7);
                const unsigned offA = a >> 2;
                const unsigned offM = ((a >> 4) << 2) | q;
                const unsigned sA = a & 3u;
                const unsigned sM = (((a >> 3) & 1u) << 1) | ((a >> 2) & 1u);
                gp[c] = mA ? (tA + offA) : (tM + offM);
                s0[c] = mA ? sA : sM;
            }
        }

        // Issue all loads back-to-back (predicated) to keep MLP high.
        uint4 qv[4];
        #pragma unroll
        for (int c = 0; c < 4; ++c) if (prd) qv[c] = __ldg(gp[c]);
        unsigned u0[4], u1[4];
        #pragma unroll
        for (int c = 0; c < 4; ++c) {
            if (!prd) {
                u0[c] = __ldg(tbl + av[c]);
                u1[c] = __ldg(tbl + ((av[c] ^ m) & HASH_MASK));
            }
        }

        float2 f[8];
        #pragma unroll
        for (int c = 0; c < 4; ++c) {
            if (prd) {
                f[c]     = h2f(comp4(qv[c], s0[c]));
                f[4 + c] = h2f(comp4(qv[c], s0[c] ^ sxor));
            } else {
                f[c]     = h2f(u0[c]);
                f[4 + c] = h2f(u1[c]);
            }
        }

        // Trilinear blend (z fastest among the 4 combos, x split at f[4..7]).
        const float wx1 = fx, wx0 = 1.0f - fx;
        const float wy1 = fy, wy0 = 1.0f - fy;
        const float wz1 = fz, wz0 = 1.0f - fz;
        const float wxy00 = wx0 * wy0, wxy01 = wx0 * wy1;
        const float wxy10 = wx1 * wy0, wxy11 = wx1 * wy1;
        float w[8];
        w[0] = wxy00 * wz0; w[1] = wxy00 * wz1;
        w[2] = wxy01 * wz0; w[3] = wxy01 * wz1;
        w[4] = wxy10 * wz0; w[5] = wxy10 * wz1;
        w[6] = wxy11 * wz0; w[7] = wxy11 * wz1;

        float r0 = w[0] * f[0].x;
        float r1 = w[0] * f[0].y;
        #pragma unroll
        for (int j = 1; j < 8; ++j) {
            r0 = fmaf(w[j], f[j].x, r0);
            r1 = fmaf(w[j], f[j].y, r1);
        }

        sbuf[tid * 33 + 2 * l + 0] = r0;
        sbuf[tid * 33 + 2 * l + 1] = r1;
    }

    __syncthreads();

    // Coalesced copy-out; streaming stores keep tables resident in L2.
    const int nvalid = min(BLOCK_T, n - p0);
    float* __restrict__ ob = out + (size_t)p0 * 32;
    const int total = nvalid * 32;
    #pragma unroll 4
    for (int k = tid; k < total; k += BLOCK_T) {
        __stcs(ob + k, sbuf[(k >> 5) * 33 + (k & 31)]);
    }
}

extern "C" void kernel_launch(void* const* d_in, const int* in_sizes, int n_in,
                              void* d_out, int out_size)
{
    const int n = out_size / (L_LEVELS * 2);   // out is [N, 32] float32

    const float* x   = (const float*)d_in[0];
    const float* tbl = (const float*)d_in[1];
    if (n_in >= 2 && in_sizes[0] != n * 3) {
        x   = (const float*)d_in[1];
        tbl = (const float*)d_in[0];
    }

    LevelParams lp;
    const double B = pow(2.0, 7.0 / 15.0);     // log2(2048/16)/15
    int off = 0;
    for (int l = 0; l < L_LEVELS; ++l) {
        const double s = 16.0 * pow(B, (double)l) - 1.0;
        lp.scale[l] = (float)s;
        lp.res[l]   = (int)ceil(s) + 1;
        if (l < NUM_DENSE) {
            lp.doff[l] = off;
            off += lp.res[l] * lp.res[l] * lp.res[l];
        }
    }
    const int total04 = lp.doff[5];            // 330,940 (levels 0-4)
    const int total5  = off - lp.doff[5];      // 531,441 (level 5, res=81)

    // Prologues (same stream; deterministic functions of inputs).
    const int htot = NUM_HASH * (1 << 15);
    build_hash_kernel<<<(htot + 255) / 256, 256>>>(tbl);
    build_dense_kernel<<<(total04 + 255) / 256, 256>>>(tbl, lp, total04);
    build_dense5_kernel<<<(total5 + 255) / 256, 256>>>(
        tbl, lp.res[5], lp.doff[5], total5);

    const int grid = (n + BLOCK_T - 1) / BLOCK_T;
    hashgrid_kernel<<<grid, BLOCK_T>>>(x, (float*)d_out, n, lp);
}